// round 13
// baseline (speedup 1.0000x reference)
#include <cuda_runtime.h>
#include <cuda_fp16.h>
#include <cstdint>

#define NN 64
#define TT 512
#define VV 25
#define CI 3
#define CH 64
#define FF 25
#define G4 100   // 4*FF
#define MROWS ((size_t)NN * TT * VV)   // 819200
#define F1P 640  // padded f1 row stride (floats) per (n,t)

// Scratch (device globals: allocation-free per harness rules)
// g_zxh layout: [n][v][t][p], p = interleaved gate: p = 4*unit + {i,f,g,o}
__device__ __half g_zxh[(size_t)NN * VV * TT * G4];
__device__ float  g_f1[(size_t)NN * TT * F1P];

typedef unsigned long long ull;

__device__ __forceinline__ ull pack2(float a, float b) {
    ull r;
    asm("mov.b64 %0, {%1,%2};" : "=l"(r) : "r"(__float_as_uint(a)), "r"(__float_as_uint(b)));
    return r;
}
__device__ __forceinline__ void unpack2(ull p, float& a, float& b) {
    unsigned int x, y;
    asm("mov.b64 {%0,%1}, %2;" : "=r"(x), "=r"(y) : "l"(p));
    a = __uint_as_float(x); b = __uint_as_float(y);
}
__device__ __forceinline__ ull fma2(ull a, ull b, ull c) {
    ull d;
    asm("fma.rn.f32x2 %0, %1, %2, %3;" : "=l"(d) : "l"(a), "l"(b), "l"(c));
    return d;
}
__device__ __forceinline__ ull add2(ull a, ull b) {
    ull d;
    asm("add.rn.f32x2 %0, %1, %2;" : "=l"(d) : "l"(a), "l"(b));
    return d;
}
__device__ __forceinline__ float hsig(float x) {
    return fminf(fmaxf(0.2f * x + 0.5f, 0.0f), 1.0f);
}
__device__ __forceinline__ float tanh_hw(float x) {
    float y;
    asm("tanh.approx.f32 %0, %1;" : "=f"(y) : "f"(x));
    return y;
}
__device__ __forceinline__ uint32_t to_tf32(float x) {
    uint32_t r;
    asm("cvt.rna.tf32.f32 %0, %1;" : "=r"(r) : "f"(x));
    return r;
}
__device__ __forceinline__ void mma_tf32(float* c, const uint32_t* a, const uint32_t* b) {
    asm("mma.sync.aligned.m16n8k8.row.col.f32.tf32.tf32.f32 "
        "{%0,%1,%2,%3}, {%4,%5,%6,%7}, {%8,%9}, {%0,%1,%2,%3};"
        : "+f"(c[0]), "+f"(c[1]), "+f"(c[2]), "+f"(c[3])
        : "r"(a[0]), "r"(a[1]), "r"(a[2]), "r"(a[3]), "r"(b[0]), "r"(b[1]));
}
// permuted column p -> original gate index g
__device__ __forceinline__ int gate_of(int p) {
    int pc = (p > 99) ? 99 : p;
    return (pc & 3) * 25 + (pc >> 2);
}

// ---------------------------------------------------------------------------
// Kernel A: tf32 mma.sync GEMM with gate-interleaved output columns.
// zx[row, p] = (relu(x@Wc+bc) @ Wl[:, g(p)]) + bl[g(p)], stored fp16.
// ---------------------------------------------------------------------------
__global__ void __launch_bounds__(256) zx_kernel(
    const float* __restrict__ x,
    const float* __restrict__ Wc,
    const float* __restrict__ bc,
    const float* __restrict__ Wl,
    const float* __restrict__ bl)
{
    const int tid  = threadIdx.x;
    const int warp = tid >> 5;
    const int lane = tid & 31;
    const size_t base = (size_t)blockIdx.x * 128;

    const int mr = (warp & 3) * 32;
    const int nc = (warp >> 2) * 56;
    const int nn = (nc == 0) ? 7 : 6;

    __shared__ float xs[128 * CI];
    for (int i = tid; i < 128 * CI; i += 256) xs[i] = x[base * 3 + i];
    __syncthreads();

    const int r0 = mr + (lane >> 2);
    float xr[4][3];
    #pragma unroll
    for (int q = 0; q < 4; q++) {
        int r = r0 + q * 8;
        xr[q][0] = xs[r * 3 + 0];
        xr[q][1] = xs[r * 3 + 1];
        xr[q][2] = xs[r * 3 + 2];
    }

    float acc[2][7][4];
    #pragma unroll
    for (int mi = 0; mi < 2; mi++)
        #pragma unroll
        for (int ni = 0; ni < 7; ni++)
            #pragma unroll
            for (int q = 0; q < 4; q++) acc[mi][ni][q] = 0.0f;

    const int kc0 = lane & 3;
    const int bcol = nc + (lane >> 2);

    #pragma unroll
    for (int kb = 0; kb < 8; kb++) {
        const int c_lo = kb * 8 + kc0;
        const int c_hi = c_lo + 4;

        float wl0 = __ldg(&Wc[c_lo]),      wl1 = __ldg(&Wc[CH + c_lo]),
              wl2 = __ldg(&Wc[2 * CH + c_lo]), bclo = __ldg(&bc[c_lo]);
        float wh0 = __ldg(&Wc[c_hi]),      wh1 = __ldg(&Wc[CH + c_hi]),
              wh2 = __ldg(&Wc[2 * CH + c_hi]), bchi = __ldg(&bc[c_hi]);

        uint32_t a[2][4];
        #pragma unroll
        for (int mi = 0; mi < 2; mi++) {
            #pragma unroll
            for (int h = 0; h < 2; h++) {
                int q = mi * 2 + h;
                float lo = bclo + xr[q][0] * wl0 + xr[q][1] * wl1 + xr[q][2] * wl2;
                float hi = bchi + xr[q][0] * wh0 + xr[q][1] * wh1 + xr[q][2] * wh2;
                a[mi][h]     = to_tf32(fmaxf(lo, 0.0f));
                a[mi][h + 2] = to_tf32(fmaxf(hi, 0.0f));
            }
        }

        #pragma unroll
        for (int ni = 0; ni < 7; ni++) {
            if (ni >= nn) break;
            int g = gate_of(bcol + ni * 8);
            uint32_t b[2];
            b[0] = to_tf32(__ldg(&Wl[c_lo * G4 + g]));
            b[1] = to_tf32(__ldg(&Wl[c_hi * G4 + g]));
            mma_tf32(acc[0][ni], a[0], b);
            mma_tf32(acc[1][ni], a[1], b);
        }
    }

    #pragma unroll
    for (int mi = 0; mi < 2; mi++) {
        #pragma unroll
        for (int h = 0; h < 2; h++) {
            size_t row = base + r0 + mi * 16 + h * 8;
            int nt = (int)(row / VV);
            int v  = (int)(row - (size_t)nt * VV);
            int n  = nt >> 9, t = nt & 511;
            __half* dst = &g_zxh[(((size_t)n * VV + v) * TT + t) * G4];
            #pragma unroll
            for (int ni = 0; ni < 7; ni++) {
                if (ni >= nn) break;
                int p = nc + ni * 8 + 2 * (lane & 3);
                if (p < 100) {
                    float ox = acc[mi][ni][2 * h + 0] + __ldg(&bl[gate_of(p)]);
                    float oy = acc[mi][ni][2 * h + 1] + __ldg(&bl[gate_of(p + 1)]);
                    *reinterpret_cast<__half2*>(dst + p) = __floats2half2_rn(ox, oy);
                }
            }
        }
    }
}

// ---------------------------------------------------------------------------
// Kernel B: warp-per-(n,v) LSTM scan. Interleaved fp16 zx: one LDG.64 per
// lane per step delivers (i,f,g,o) for unit j. Depth-8 register ring.
// ---------------------------------------------------------------------------
__global__ void __launch_bounds__(64) lstm_kernel(
    const float* __restrict__ U)
{
    const int lane = threadIdx.x & 31;
    const int warp = threadIdx.x >> 5;
    const int nv = blockIdx.x * 2 + warp;
    const int n = nv / VV, v = nv % VV;
    const int j = (lane < FF) ? lane : 0;
    const bool act = (lane < FF);

    ull u_if[FF], u_go[FF];
    #pragma unroll
    for (int f = 0; f < FF; f++) {
        u_if[f] = pack2(U[f * G4 + j],          U[f * G4 + FF + j]);
        u_go[f] = pack2(U[f * G4 + 2 * FF + j], U[f * G4 + 3 * FF + j]);
    }

    const __half* zp = g_zxh + (size_t)nv * TT * G4;
    float* f1p = g_f1 + ((size_t)n * TT) * F1P + (size_t)v * FF + j;

    float h = 0.0f, c = 0.0f;

    uint2 zbuf[8];
    #pragma unroll
    for (int i = 0; i < 8; i++)
        zbuf[i] = __ldg(reinterpret_cast<const uint2*>(zp + (size_t)i * G4) + j);

    for (int tb = 0; tb < TT; tb += 8) {
        #pragma unroll
        for (int i = 0; i < 8; i++) {
            const int t = tb + i;
            uint2 zz = zbuf[i];

            if (t + 8 < TT)
                zbuf[i] = __ldg(reinterpret_cast<const uint2*>(zp + (size_t)(t + 8) * G4) + j);

            float2 zif = __half22float2(*reinterpret_cast<__half2*>(&zz.x));
            float2 zgo = __half22float2(*reinterpret_cast<__half2*>(&zz.y));

            ull if0 = pack2(zif.x, zif.y), if1 = 0;
            ull go0 = pack2(zgo.x, zgo.y), go1 = 0;
            #pragma unroll
            for (int f = 0; f < 12; f++) {
                float hb = __shfl_sync(0xffffffffu, h, f);
                ull hh = pack2(hb, hb);
                if0 = fma2(hh, u_if[f], if0);
                go0 = fma2(hh, u_go[f], go0);
            }
            #pragma unroll
            for (int f = 12; f < FF; f++) {
                float hb = __shfl_sync(0xffffffffu, h, f);
                ull hh = pack2(hb, hb);
                if1 = fma2(hh, u_if[f], if1);
                go1 = fma2(hh, u_go[f], go1);
            }
            ull acc_if = add2(if0, if1);
            ull acc_go = add2(go0, go1);

            float gi, gf, gg, go;
            unpack2(acc_if, gi, gf);
            unpack2(acc_go, gg, go);
            c = hsig(gf) * c + hsig(gi) * tanh_hw(gg);
            h = hsig(go) * tanh_hw(c);
            if (act) f1p[(size_t)t * F1P] = h;
        }
    }
}

// ---------------------------------------------------------------------------
// Kernel C: tensor-core attention (R11-passing version).
// ---------------------------------------------------------------------------
__global__ void __launch_bounds__(128) attn_kernel(
    const float* __restrict__ x,
    const float* __restrict__ Wc,
    const float* __restrict__ bc,
    const float* __restrict__ bias,
    float* __restrict__ out)
{
    const int tid = threadIdx.x;
    const int warp = tid >> 5, lane = tid & 31;
    const int nt = blockIdx.x * 4 + warp;

    __shared__ float Wcs[CI * CH];
    __shared__ float bcs[CH];
    __shared__ __align__(16) float f1s[4][F1P];
    __shared__ float xss[4][76];
    __shared__ float cfs[4][32][36];

    for (int i = tid; i < CI * CH; i += 128) Wcs[i] = Wc[i];
    if (tid < CH) bcs[tid] = bc[tid];

    {
        const float4* src = reinterpret_cast<const float4*>(g_f1 + (size_t)nt * F1P);
        float4* dst = reinterpret_cast<float4*>(f1s[warp]);
        for (int i = lane; i < F1P / 4; i += 32) dst[i] = src[i];
        for (int i = lane; i < VV * CI; i += 32) xss[warp][i] = x[(size_t)nt * (VV * CI) + i];
    }
    __syncthreads();

    if (lane < VV) {
        float e[FF];
        float mx = -1e30f;
        const float* fr = &f1s[warp][lane * FF];
        const float* br = bias + lane * VV;
        #pragma unroll
        for (int w = 0; w < FF; w++) {
            float f = fr[w];
            f = (f > 0.0f) ? f : 0.2f * f;
            f += __ldg(&br[w]);
            e[w] = f;
            mx = fmaxf(mx, f);
        }
        float s = 0.0f;
        #pragma unroll
        for (int w = 0; w < FF; w++) { e[w] = __expf(e[w] - mx); s += e[w]; }
        float inv = __fdividef(1.0f, s);
        #pragma unroll
        for (int w = 0; w < FF; w++)
            cfs[warp][lane][w] = __uint_as_float(to_tf32(e[w] * inv));
        #pragma unroll
        for (int w = FF; w < 32; w++) cfs[warp][lane][w] = 0.0f;
    }
    __syncwarp();

    const int g = lane >> 2, kq = lane & 3;
    uint32_t af[2][4][4];
    #pragma unroll
    for (int mi = 0; mi < 2; mi++)
        #pragma unroll
        for (int ki = 0; ki < 4; ki++) {
            af[mi][ki][0] = __float_as_uint(cfs[warp][16 * mi + g    ][8 * ki + kq]);
            af[mi][ki][1] = __float_as_uint(cfs[warp][16 * mi + g + 8][8 * ki + kq]);
            af[mi][ki][2] = __float_as_uint(cfs[warp][16 * mi + g    ][8 * ki + kq + 4]);
            af[mi][ki][3] = __float_as_uint(cfs[warp][16 * mi + g + 8][8 * ki + kq + 4]);
        }

    float xw0[8], xw1[8], xw2[8];
    bool wok[8];
    #pragma unroll
    for (int jj = 0; jj < 8; jj++) {
        int w = kq + 4 * jj;
        int wc = (w < VV) ? w : 0;
        xw0[jj] = xss[warp][wc * 3 + 0];
        xw1[jj] = xss[warp][wc * 3 + 1];
        xw2[jj] = xss[warp][wc * 3 + 2];
        wok[jj] = (w < VV);
    }

    float* obase = out + (size_t)nt * (VV * CH);

    #pragma unroll
    for (int ni = 0; ni < 8; ni++) {
        const int d = 8 * ni + g;
        const float w0 = Wcs[d], w1 = Wcs[CH + d], w2 = Wcs[2 * CH + d], bd = bcs[d];

        float acc0[4] = {0.f, 0.f, 0.f, 0.f};
        float acc1[4] = {0.f, 0.f, 0.f, 0.f};

        #pragma unroll
        for (int ki = 0; ki < 4; ki++) {
            float v0 = bd + xw0[2 * ki] * w0 + xw1[2 * ki] * w1 + xw2[2 * ki] * w2;
            float v1 = bd + xw0[2 * ki + 1] * w0 + xw1[2 * ki + 1] * w1 + xw2[2 * ki + 1] * w2;
            v0 = wok[2 * ki]     ? fmaxf(v0, 0.0f) : 0.0f;
            v1 = wok[2 * ki + 1] ? fmaxf(v1, 0.0f) : 0.0f;
            uint32_t b[2];
            b[0] = to_tf32(v0);
            b[1] = to_tf32(v1);
            mma_tf32(acc0, af[0][ki], b);
            mma_tf32(acc1, af[1][ki], b);
        }

        const int col = 8 * ni + 2 * kq;
        *reinterpret_cast<float2*>(obase + (size_t)(g)      * CH + col) = make_float2(acc0[0], acc0[1]);
        *reinterpret_cast<float2*>(obase + (size_t)(g + 8)  * CH + col) = make_float2(acc0[2], acc0[3]);
        *reinterpret_cast<float2*>(obase + (size_t)(g + 16) * CH + col) = make_float2(acc1[0], acc1[1]);
        if (g == 0)
            *reinterpret_cast<float2*>(obase + (size_t)24 * CH + col)   = make_float2(acc1[2], acc1[3]);
    }
}

// ---------------------------------------------------------------------------
extern "C" void kernel_launch(void* const* d_in, const int* in_sizes, int n_in,
                              void* d_out, int out_size) {
    const float* x    = (const float*)d_in[0];
    const float* Wc   = (const float*)d_in[1];
    const float* bc   = (const float*)d_in[2];
    const float* Wl   = (const float*)d_in[3];
    const float* U    = (const float*)d_in[4];
    const float* bl   = (const float*)d_in[5];
    const float* bias = (const float*)d_in[6];
    float* out = (float*)d_out;

    zx_kernel<<<(int)(MROWS / 128), 256>>>(x, Wc, bc, Wl, bl);
    lstm_kernel<<<NN * VV / 2, 64>>>(U);
    attn_kernel<<<NN * TT / 4, 128>>>(x, Wc, bc, bias, out);
}